// round 5
// baseline (speedup 1.0000x reference)
#include <cuda_runtime.h>
#include <cuda_fp16.h>
#include <cstdint>
#include <math.h>

#define Bc 2
#define Tc 2048
#define Dc 1024
#define Hc 16
#define DH 64
#define Mtot (Bc*Tc)   // 4096

// Scratch (allocation-free)
__device__ float g_q [Bc*Hc*Tc*DH];
__device__ float g_k [Bc*Hc*Tc*DH];
__device__ float g_v [Bc*Hc*Tc*DH];
__device__ float g_ao[Bc*Tc*Dc];

// ---------------- fp16 mma.sync GEMM: C = A @ W^T ----------------
// A: M x 1024 row-major fp32, W: 1024 x 1024 row-major fp32.
// Tile 128x128x32. 8 warps = 2(m) x 4(n), warp tile 64x32, frags m16n8k16.
// SMEM: halves, row stride 40 halves (80B) -> conflict-free operand LDS.
// Double buffered: 2 bufs * 2 mats * 128 rows * 80B = 40960 B.

#define RS 40                       // row stride in halves
#define TILE_H (128*RS)             // halves per tile buffer (5120)
#define SMEM_BYTES (2*2*128*80)     // 40960

__device__ __forceinline__ void mma16(float* c, const uint32_t* a, const uint32_t* b) {
    asm volatile(
        "mma.sync.aligned.m16n8k16.row.col.f32.f16.f16.f32 "
        "{%0,%1,%2,%3}, {%4,%5,%6,%7}, {%8,%9}, {%0,%1,%2,%3};"
        : "+f"(c[0]), "+f"(c[1]), "+f"(c[2]), "+f"(c[3])
        : "r"(a[0]), "r"(a[1]), "r"(a[2]), "r"(a[3]), "r"(b[0]), "r"(b[1]));
}

template<int OUTSEL, int ASEL, int PERM>
__global__ __launch_bounds__(256) void gemm_mma(const float* __restrict__ Aext,
                                                const float* __restrict__ W,
                                                float* __restrict__ Cext) {
    extern __shared__ __half sm[];   // [buf][mat][128][RS]
    const float* A = (ASEL == 1) ? g_ao : Aext;
    float* C = (OUTSEL == 0) ? g_q : (OUTSEL == 1) ? g_k : (OUTSEL == 2) ? g_v : Cext;

    const int tid = threadIdx.x;
    const int wid = tid >> 5, lane = tid & 31;
    const int row0 = blockIdx.y * 128;
    const int col0 = blockIdx.x * 128;
    const int wm = (wid & 1) * 64;        // warp m offset
    const int wn = (wid >> 1) * 32;       // warp n offset
    const int g = lane >> 2, tig = lane & 3;

    // loader mapping: 2 threads per row, 16 consecutive floats each (coalesced)
    const int lr = tid >> 1;              // 0..127
    const int lc = (tid & 1) * 16;        // float col base within 32

    const float* Ag = A + (size_t)(row0 + lr) * Dc + lc;
    const float* Bg = W + (size_t)(col0 + lr) * Dc + lc;

    float acc[4][4][4];
    #pragma unroll
    for (int i = 0; i < 4; i++)
        #pragma unroll
        for (int j = 0; j < 4; j++)
            #pragma unroll
            for (int k = 0; k < 4; k++) acc[i][j][k] = 0.f;

    float4 pa[4], pb[4];

    auto ldg_tile = [&](const float* Ap, const float* Bp) {
        #pragma unroll
        for (int i = 0; i < 4; i++) {
            pa[i] = *(const float4*)(Ap + 4 * i);
            pb[i] = *(const float4*)(Bp + 4 * i);
        }
    };
    auto sts_tile = [&](int buf) {
        __half* Ad = sm + buf * 2 * TILE_H + lr * RS + lc;
        __half* Bd = sm + buf * 2 * TILE_H + TILE_H + lr * RS + lc;
        __half2 ha[8], hb[8];
        #pragma unroll
        for (int i = 0; i < 4; i++) {
            ha[2*i]   = __floats2half2_rn(pa[i].x, pa[i].y);
            ha[2*i+1] = __floats2half2_rn(pa[i].z, pa[i].w);
            hb[2*i]   = __floats2half2_rn(pb[i].x, pb[i].y);
            hb[2*i+1] = __floats2half2_rn(pb[i].z, pb[i].w);
        }
        *(uint4*)(Ad)     = *(uint4*)&ha[0];
        *(uint4*)(Ad + 8) = *(uint4*)&ha[4];
        *(uint4*)(Bd)     = *(uint4*)&hb[0];
        *(uint4*)(Bd + 8) = *(uint4*)&hb[4];
    };

    ldg_tile(Ag, Bg);
    sts_tile(0);
    __syncthreads();

    for (int kt = 0; kt < 32; kt++) {
        if (kt + 1 < 32) ldg_tile(Ag + (kt + 1) * 32, Bg + (kt + 1) * 32);

        const __half* Ab = sm + (kt & 1) * 2 * TILE_H;
        const __half* Bb = Ab + TILE_H;

        #pragma unroll
        for (int ks = 0; ks < 2; ks++) {
            const int k0 = ks * 16;
            uint32_t af[4][4], bf[4][2];
            #pragma unroll
            for (int mi = 0; mi < 4; mi++) {
                const int r = wm + mi * 16 + g;
                af[mi][0] = *(const uint32_t*)(Ab + r * RS + k0 + 2 * tig);
                af[mi][1] = *(const uint32_t*)(Ab + (r + 8) * RS + k0 + 2 * tig);
                af[mi][2] = *(const uint32_t*)(Ab + r * RS + k0 + 2 * tig + 8);
                af[mi][3] = *(const uint32_t*)(Ab + (r + 8) * RS + k0 + 2 * tig + 8);
            }
            #pragma unroll
            for (int ni = 0; ni < 4; ni++) {
                const int rn = wn + ni * 8 + g;
                bf[ni][0] = *(const uint32_t*)(Bb + rn * RS + k0 + 2 * tig);
                bf[ni][1] = *(const uint32_t*)(Bb + rn * RS + k0 + 2 * tig + 8);
            }
            #pragma unroll
            for (int mi = 0; mi < 4; mi++)
                #pragma unroll
                for (int ni = 0; ni < 4; ni++)
                    mma16(acc[mi][ni], af[mi], bf[ni]);
        }

        if (kt + 1 < 32) sts_tile((kt + 1) & 1);
        __syncthreads();
    }

    // epilogue: m16n8 frag: c0/c1 at (g, 2tig[+1]), c2/c3 at (g+8, ...)
    #pragma unroll
    for (int mi = 0; mi < 4; mi++) {
        #pragma unroll
        for (int ni = 0; ni < 4; ni++) {
            const int m0 = row0 + wm + mi * 16 + g;
            const int n  = col0 + wn + ni * 8 + tig * 2;
            float2 v01 = make_float2(acc[mi][ni][0], acc[mi][ni][1]);
            float2 v23 = make_float2(acc[mi][ni][2], acc[mi][ni][3]);
            if (PERM) {
                const int b0i = m0 >> 11, t0 = m0 & 2047;
                const int h = n / DH, d0 = n % DH;
                float* p0 = C + ((((size_t)(b0i * Hc + h)) * Tc + t0) * DH + d0);
                *(float2*)p0 = v01;
                const int m1 = m0 + 8;
                const int b1i = m1 >> 11, t1 = m1 & 2047;
                float* p1 = C + ((((size_t)(b1i * Hc + h)) * Tc + t1) * DH + d0);
                *(float2*)p1 = v23;
            } else {
                *(float2*)(C + (size_t)m0 * Dc + n) = v01;
                *(float2*)(C + (size_t)(m0 + 8) * Dc + n) = v23;
            }
        }
    }
}

// ---------------- attention (unchanged) ----------------
__global__ __launch_bounds__(64) void attn_kernel() {
    const int b = blockIdx.z;
    const int h = blockIdx.y;
    const int t = blockIdx.x * 64 + threadIdx.x;

    const size_t head_off = ((size_t)(b * Hc + h)) * Tc * DH;
    const float* qp = g_q + head_off + (size_t)t * DH;
    const float* kb = g_k + head_off;
    const float* vb = g_v + head_off;

    float qr[DH];
    #pragma unroll
    for (int d = 0; d < DH; d++) qr[d] = qp[d];

    float mval = -1e30f, l = 0.f;
    float acc[DH];
    #pragma unroll
    for (int d = 0; d < DH; d++) acc[d] = 0.f;

    int j0 = t - 128; if (j0 < 0) j0 = 0;

    for (int j = j0; j <= t; j++) {
        const float4* kp = (const float4*)(kb + (size_t)j * DH);
        float s = 0.f;
        #pragma unroll
        for (int d4 = 0; d4 < 16; d4++) {
            float4 kv4 = kp[d4];
            s = fmaf(qr[4 * d4 + 0], kv4.x, s);
            s = fmaf(qr[4 * d4 + 1], kv4.y, s);
            s = fmaf(qr[4 * d4 + 2], kv4.z, s);
            s = fmaf(qr[4 * d4 + 3], kv4.w, s);
        }
        s *= 0.125f;

        float mn   = fmaxf(mval, s);
        float corr = __expf(mval - mn);
        float p    = __expf(s - mn);
        l = l * corr + p;

        const float4* vp = (const float4*)(vb + (size_t)j * DH);
        #pragma unroll
        for (int d4 = 0; d4 < 16; d4++) {
            float4 vv = vp[d4];
            acc[4 * d4 + 0] = fmaf(acc[4 * d4 + 0], corr, p * vv.x);
            acc[4 * d4 + 1] = fmaf(acc[4 * d4 + 1], corr, p * vv.y);
            acc[4 * d4 + 2] = fmaf(acc[4 * d4 + 2], corr, p * vv.z);
            acc[4 * d4 + 3] = fmaf(acc[4 * d4 + 3], corr, p * vv.w);
        }
        mval = mn;
    }

    const float inv = 1.f / l;
    float* op = g_ao + ((size_t)b * Tc + t) * Dc + h * DH;
    #pragma unroll
    for (int d = 0; d < DH; d++) op[d] = acc[d] * inv;
}

extern "C" void kernel_launch(void* const* d_in, const int* in_sizes, int n_in,
                              void* d_out, int out_size) {
    const float* x  = (const float*)d_in[0];
    const float* Wq = (const float*)d_in[1];
    const float* Wk = (const float*)d_in[2];
    const float* Wv = (const float*)d_in[3];
    const float* Wo = (const float*)d_in[4];
    float* out = (float*)d_out;

    dim3 gg(Dc / 128, Mtot / 128);   // (8, 32) = 256 CTAs
    gemm_mma<0,0,1><<<gg, 256, SMEM_BYTES>>>(x, Wq, nullptr);
    gemm_mma<1,0,1><<<gg, 256, SMEM_BYTES>>>(x, Wk, nullptr);
    gemm_mma<2,0,1><<<gg, 256, SMEM_BYTES>>>(x, Wv, nullptr);

    attn_kernel<<<dim3(Tc / 64, Hc, Bc), 64>>>();

    gemm_mma<3,1,0><<<gg, 256, SMEM_BYTES>>>(nullptr, Wo, out);
}

// round 7
// speedup vs baseline: 3.3662x; 3.3662x over previous
#include <cuda_runtime.h>
#include <cuda_fp16.h>
#include <cstdint>
#include <math.h>

#define Bc 2
#define Tc 2048
#define Dc 1024
#define Hc 16
#define DH 64
#define Mtot (Bc*Tc)   // 4096

// Scratch (allocation-free)
__device__ float g_q [Bc*Hc*Tc*DH];
__device__ float g_k [Bc*Hc*Tc*DH];
__device__ float g_v [Bc*Hc*Tc*DH];
__device__ float g_ao[Bc*Tc*Dc];

// ---------------- fp16 mma.sync GEMM: C = A @ W^T (unchanged from R5) ----------------
#define RS 40
#define TILE_H (128*RS)
#define SMEM_BYTES (2*2*128*80)     // 40960

__device__ __forceinline__ void mma16(float* c, const uint32_t* a, const uint32_t* b) {
    asm volatile(
        "mma.sync.aligned.m16n8k16.row.col.f32.f16.f16.f32 "
        "{%0,%1,%2,%3}, {%4,%5,%6,%7}, {%8,%9}, {%0,%1,%2,%3};"
        : "+f"(c[0]), "+f"(c[1]), "+f"(c[2]), "+f"(c[3])
        : "r"(a[0]), "r"(a[1]), "r"(a[2]), "r"(a[3]), "r"(b[0]), "r"(b[1]));
}

template<int OUTSEL, int ASEL, int PERM>
__global__ __launch_bounds__(256) void gemm_mma(const float* __restrict__ Aext,
                                                const float* __restrict__ W,
                                                float* __restrict__ Cext) {
    extern __shared__ __half sm[];
    const float* A = (ASEL == 1) ? g_ao : Aext;
    float* C = (OUTSEL == 0) ? g_q : (OUTSEL == 1) ? g_k : (OUTSEL == 2) ? g_v : Cext;

    const int tid = threadIdx.x;
    const int wid = tid >> 5, lane = tid & 31;
    const int row0 = blockIdx.y * 128;
    const int col0 = blockIdx.x * 128;
    const int wm = (wid & 1) * 64;
    const int wn = (wid >> 1) * 32;
    const int g = lane >> 2, tig = lane & 3;

    const int lr = tid >> 1;
    const int lc = (tid & 1) * 16;

    const float* Ag = A + (size_t)(row0 + lr) * Dc + lc;
    const float* Bg = W + (size_t)(col0 + lr) * Dc + lc;

    float acc[4][4][4];
    #pragma unroll
    for (int i = 0; i < 4; i++)
        #pragma unroll
        for (int j = 0; j < 4; j++)
            #pragma unroll
            for (int k = 0; k < 4; k++) acc[i][j][k] = 0.f;

    float4 pa[4], pb[4];

    auto ldg_tile = [&](const float* Ap, const float* Bp) {
        #pragma unroll
        for (int i = 0; i < 4; i++) {
            pa[i] = *(const float4*)(Ap + 4 * i);
            pb[i] = *(const float4*)(Bp + 4 * i);
        }
    };
    auto sts_tile = [&](int buf) {
        __half* Ad = sm + buf * 2 * TILE_H + lr * RS + lc;
        __half* Bd = sm + buf * 2 * TILE_H + TILE_H + lr * RS + lc;
        __half2 ha[8], hb[8];
        #pragma unroll
        for (int i = 0; i < 4; i++) {
            ha[2*i]   = __floats2half2_rn(pa[i].x, pa[i].y);
            ha[2*i+1] = __floats2half2_rn(pa[i].z, pa[i].w);
            hb[2*i]   = __floats2half2_rn(pb[i].x, pb[i].y);
            hb[2*i+1] = __floats2half2_rn(pb[i].z, pb[i].w);
        }
        *(uint4*)(Ad)     = *(uint4*)&ha[0];
        *(uint4*)(Ad + 8) = *(uint4*)&ha[4];
        *(uint4*)(Bd)     = *(uint4*)&hb[0];
        *(uint4*)(Bd + 8) = *(uint4*)&hb[4];
    };

    ldg_tile(Ag, Bg);
    sts_tile(0);
    __syncthreads();

    for (int kt = 0; kt < 32; kt++) {
        if (kt + 1 < 32) ldg_tile(Ag + (kt + 1) * 32, Bg + (kt + 1) * 32);

        const __half* Ab = sm + (kt & 1) * 2 * TILE_H;
        const __half* Bb = Ab + TILE_H;

        #pragma unroll
        for (int ks = 0; ks < 2; ks++) {
            const int k0 = ks * 16;
            uint32_t af[4][4], bf[4][2];
            #pragma unroll
            for (int mi = 0; mi < 4; mi++) {
                const int r = wm + mi * 16 + g;
                af[mi][0] = *(const uint32_t*)(Ab + r * RS + k0 + 2 * tig);
                af[mi][1] = *(const uint32_t*)(Ab + (r + 8) * RS + k0 + 2 * tig);
                af[mi][2] = *(const uint32_t*)(Ab + r * RS + k0 + 2 * tig + 8);
                af[mi][3] = *(const uint32_t*)(Ab + (r + 8) * RS + k0 + 2 * tig + 8);
            }
            #pragma unroll
            for (int ni = 0; ni < 4; ni++) {
                const int rn = wn + ni * 8 + g;
                bf[ni][0] = *(const uint32_t*)(Bb + rn * RS + k0 + 2 * tig);
                bf[ni][1] = *(const uint32_t*)(Bb + rn * RS + k0 + 2 * tig + 8);
            }
            #pragma unroll
            for (int mi = 0; mi < 4; mi++)
                #pragma unroll
                for (int ni = 0; ni < 4; ni++)
                    mma16(acc[mi][ni], af[mi], bf[ni]);
        }

        if (kt + 1 < 32) sts_tile((kt + 1) & 1);
        __syncthreads();
    }

    #pragma unroll
    for (int mi = 0; mi < 4; mi++) {
        #pragma unroll
        for (int ni = 0; ni < 4; ni++) {
            const int m0 = row0 + wm + mi * 16 + g;
            const int n  = col0 + wn + ni * 8 + tig * 2;
            float2 v01 = make_float2(acc[mi][ni][0], acc[mi][ni][1]);
            float2 v23 = make_float2(acc[mi][ni][2], acc[mi][ni][3]);
            if (PERM) {
                const int b0i = m0 >> 11, t0 = m0 & 2047;
                const int h = n / DH, d0 = n % DH;
                float* p0 = C + ((((size_t)(b0i * Hc + h)) * Tc + t0) * DH + d0);
                *(float2*)p0 = v01;
                const int m1 = m0 + 8;
                const int b1i = m1 >> 11, t1 = m1 & 2047;
                float* p1 = C + ((((size_t)(b1i * Hc + h)) * Tc + t1) * DH + d0);
                *(float2*)p1 = v23;
            } else {
                *(float2*)(C + (size_t)m0 * Dc + n) = v01;
                *(float2*)(C + (size_t)(m0 + 8) * Dc + n) = v23;
            }
        }
    }
}

// ---------------- tiled flash attention ----------------
// Block: 128 threads, one (b, h, 64-query tile). Window per query i: j in [i-128, i].
// Key tiles: 3 x 64 covering [t0-128, t0+63].
// smem: Qt[d][q], Kt[d][k] (transposed), Vs[k][d], Pt[k][q]; stride 68 floats.
#define ATS 68
#define ATT_SMEM (4*64*ATS*4)   // 69632 bytes

__global__ __launch_bounds__(128) void attn_tile() {
    extern __shared__ float smA[];
    float* Qt = smA;                 // [64 d][ATS]
    float* Kt = Qt + 64 * ATS;       // [64 d][ATS]
    float* Vs = Kt + 64 * ATS;       // [64 k][ATS]
    float* Pt = Vs + 64 * ATS;       // [64 k][ATS]

    const int b = blockIdx.z, h = blockIdx.y;
    const int t0 = blockIdx.x * 64;
    const int tid = threadIdx.x;
    const int tx = tid & 7;          // 8 cols of 8
    const int ty = tid >> 3;         // 16 rows of 4

    const size_t head_off = ((size_t)(b * Hc + h)) * Tc * DH;
    const float* qg = g_q + head_off;
    const float* kg = g_k + head_off;
    const float* vg = g_v + head_off;

    const int lr = tid >> 1;         // 0..63 staging row
    const int lcb = (tid & 1) * 32;  // float col base (half row)

    // stage Q transposed: Qt[d][q]
    {
        const float* src = qg + (size_t)(t0 + lr) * DH + lcb;
        #pragma unroll
        for (int i = 0; i < 8; i++) {
            float4 v = *(const float4*)(src + 4 * i);
            const int d = lcb + 4 * i;
            Qt[(d + 0) * ATS + lr] = v.x;
            Qt[(d + 1) * ATS + lr] = v.y;
            Qt[(d + 2) * ATS + lr] = v.z;
            Qt[(d + 3) * ATS + lr] = v.w;
        }
    }

    float m[4], l[4], acc[4][8];
    #pragma unroll
    for (int i = 0; i < 4; i++) {
        m[i] = -1e30f; l[i] = 0.f;
        #pragma unroll
        for (int j = 0; j < 8; j++) acc[i][j] = 0.f;
    }

    #pragma unroll 1
    for (int kt = 0; kt < 3; kt++) {
        const int kb = t0 - 128 + 64 * kt;

        // stage K transposed + V natural
        {
            const int gr = kb + lr;
            const int grc = gr < 0 ? 0 : gr;
            const float* ksrc = kg + (size_t)grc * DH + lcb;
            const float* vsrc = vg + (size_t)grc * DH + lcb;
            #pragma unroll
            for (int i = 0; i < 8; i++) {
                float4 kv = *(const float4*)(ksrc + 4 * i);
                const int d = lcb + 4 * i;
                Kt[(d + 0) * ATS + lr] = kv.x;
                Kt[(d + 1) * ATS + lr] = kv.y;
                Kt[(d + 2) * ATS + lr] = kv.z;
                Kt[(d + 3) * ATS + lr] = kv.w;
                float4 vv = *(const float4*)(vsrc + 4 * i);
                *(float4*)(Vs + lr * ATS + d) = vv;
            }
        }
        __syncthreads();

        // S = Q @ K^T for this tile: thread owns rows 4ty..+3, cols 8tx..+7
        float s[4][8];
        #pragma unroll
        for (int i = 0; i < 4; i++)
            #pragma unroll
            for (int j = 0; j < 8; j++) s[i][j] = 0.f;

        #pragma unroll 4
        for (int kk = 0; kk < 64; kk++) {
            float4 qv = *(const float4*)(Qt + kk * ATS + 4 * ty);
            float4 k0 = *(const float4*)(Kt + kk * ATS + 8 * tx);
            float4 k1 = *(const float4*)(Kt + kk * ATS + 8 * tx + 4);
            const float qr[4] = {qv.x, qv.y, qv.z, qv.w};
            const float kr[8] = {k0.x, k0.y, k0.z, k0.w, k1.x, k1.y, k1.z, k1.w};
            #pragma unroll
            for (int i = 0; i < 4; i++)
                #pragma unroll
                for (int j = 0; j < 8; j++)
                    s[i][j] = fmaf(qr[i], kr[j], s[i][j]);
        }

        // mask + online softmax per row
        #pragma unroll
        for (int i = 0; i < 4; i++) {
            const int iq = t0 + 4 * ty + i;
            #pragma unroll
            for (int j = 0; j < 8; j++) {
                const int jq = kb + 8 * tx + j;
                const bool ok = (jq >= 0) & (jq <= iq) & (iq - jq <= 128);
                s[i][j] = ok ? s[i][j] * 0.125f : -1e30f;
            }
            float rmax = s[i][0];
            #pragma unroll
            for (int j = 1; j < 8; j++) rmax = fmaxf(rmax, s[i][j]);
            rmax = fmaxf(rmax, __shfl_xor_sync(0xffffffffu, rmax, 1));
            rmax = fmaxf(rmax, __shfl_xor_sync(0xffffffffu, rmax, 2));
            rmax = fmaxf(rmax, __shfl_xor_sync(0xffffffffu, rmax, 4));

            const float mn = fmaxf(m[i], rmax);
            const float corr = __expf(m[i] - mn);
            float rsum = 0.f;
            float p[8];
            #pragma unroll
            for (int j = 0; j < 8; j++) {
                p[j] = (s[i][j] > -1e29f) ? __expf(s[i][j] - mn) : 0.f;
                rsum += p[j];
            }
            rsum += __shfl_xor_sync(0xffffffffu, rsum, 1);
            rsum += __shfl_xor_sync(0xffffffffu, rsum, 2);
            rsum += __shfl_xor_sync(0xffffffffu, rsum, 4);
            l[i] = l[i] * corr + rsum;
            m[i] = mn;
            #pragma unroll
            for (int j = 0; j < 8; j++) acc[i][j] *= corr;
            // write P transposed: Pt[k][q]
            #pragma unroll
            for (int j = 0; j < 8; j++)
                Pt[(8 * tx + j) * ATS + 4 * ty + i] = p[j];
        }
        __syncthreads();

        // O += P @ V: thread owns rows 4ty..+3 (q), cols 8tx..+7 (d)
        #pragma unroll 4
        for (int kk = 0; kk < 64; kk++) {
            float4 pv = *(const float4*)(Pt + kk * ATS + 4 * ty);
            float4 v0 = *(const float4*)(Vs + kk * ATS + 8 * tx);
            float4 v1 = *(const float4*)(Vs + kk * ATS + 8 * tx + 4);
            const float pr[4] = {pv.x, pv.y, pv.z, pv.w};
            const float vr[8] = {v0.x, v0.y, v0.z, v0.w, v1.x, v1.y, v1.z, v1.w};
            #pragma unroll
            for (int i = 0; i < 4; i++)
                #pragma unroll
                for (int j = 0; j < 8; j++)
                    acc[i][j] = fmaf(pr[i], vr[j], acc[i][j]);
        }
        __syncthreads();
    }

    // write O to g_ao (B,T,D)
    #pragma unroll
    for (int i = 0; i < 4; i++) {
        const float inv = 1.f / l[i];
        float* dst = g_ao + ((size_t)b * Tc + t0 + 4 * ty + i) * Dc + h * DH + 8 * tx;
        float4 o0 = make_float4(acc[i][0] * inv, acc[i][1] * inv, acc[i][2] * inv, acc[i][3] * inv);
        float4 o1 = make_float4(acc[i][4] * inv, acc[i][5] * inv, acc[i][6] * inv, acc[i][7] * inv);
        *(float4*)dst = o0;
        *(float4*)(dst + 4) = o1;
    }
}

extern "C" void kernel_launch(void* const* d_in, const int* in_sizes, int n_in,
                              void* d_out, int out_size) {
    const float* x  = (const float*)d_in[0];
    const float* Wq = (const float*)d_in[1];
    const float* Wk = (const float*)d_in[2];
    const float* Wv = (const float*)d_in[3];
    const float* Wo = (const float*)d_in[4];
    float* out = (float*)d_out;

    cudaFuncSetAttribute(attn_tile, cudaFuncAttributeMaxDynamicSharedMemorySize, ATT_SMEM);

    dim3 gg(Dc / 128, Mtot / 128);   // (8, 32) = 256 CTAs
    gemm_mma<0,0,1><<<gg, 256, SMEM_BYTES>>>(x, Wq, nullptr);
    gemm_mma<1,0,1><<<gg, 256, SMEM_BYTES>>>(x, Wk, nullptr);
    gemm_mma<2,0,1><<<gg, 256, SMEM_BYTES>>>(x, Wv, nullptr);

    attn_tile<<<dim3(Tc / 64, Hc, Bc), 128, ATT_SMEM>>>();

    gemm_mma<3,1,0><<<gg, 256, SMEM_BYTES>>>(nullptr, Wo, out);
}

// round 8
// speedup vs baseline: 6.5118x; 1.9344x over previous
#include <cuda_runtime.h>
#include <cuda_fp16.h>
#include <cstdint>
#include <math.h>

#define Bc 2
#define Tc 2048
#define Dc 1024
#define Hc 16
#define DH 64
#define Mtot (Bc*Tc)   // 4096

// Scratch (allocation-free)
__device__ float  g_q  [Bc*Hc*Tc*DH];
__device__ float  g_k  [Bc*Hc*Tc*DH];
__device__ float  g_v  [Bc*Hc*Tc*DH];
__device__ __half g_xh [Mtot*Dc];        // x in fp16
__device__ __half g_wh [4*Dc*Dc];        // Wq,Wk,Wv,Wo in fp16
__device__ __half g_aoh[Bc*Tc*Dc];       // attention output in fp16

// ---------------- helpers ----------------
__device__ __forceinline__ uint32_t smem_u32(const void* p) {
    uint32_t a;
    asm("{ .reg .u64 t; cvta.to.shared.u64 t, %1; cvt.u32.u64 %0, t; }" : "=r"(a) : "l"(p));
    return a;
}
__device__ __forceinline__ void cpa16(uint32_t s, const void* gp) {
    asm volatile("cp.async.cg.shared.global [%0], [%1], 16;" :: "r"(s), "l"(gp) : "memory");
}
#define LDMX4(r, a) \
    asm volatile("ldmatrix.sync.aligned.m8n8.x4.shared.b16 {%0,%1,%2,%3}, [%4];" \
        : "=r"((r)[0]), "=r"((r)[1]), "=r"((r)[2]), "=r"((r)[3]) : "r"(a))

__device__ __forceinline__ void mma16(float* c, const uint32_t* a, const uint32_t* b) {
    asm volatile(
        "mma.sync.aligned.m16n8k16.row.col.f32.f16.f16.f32 "
        "{%0,%1,%2,%3}, {%4,%5,%6,%7}, {%8,%9}, {%0,%1,%2,%3};"
        : "+f"(c[0]), "+f"(c[1]), "+f"(c[2]), "+f"(c[3])
        : "r"(a[0]), "r"(a[1]), "r"(a[2]), "r"(a[3]), "r"(b[0]), "r"(b[1]));
}

// ---------------- fp32 -> fp16 pre-convert (x and the 4 weight matrices) ----------------
__global__ __launch_bounds__(256) void cvt_all(const float* __restrict__ x,
                                               const float* __restrict__ wq,
                                               const float* __restrict__ wk,
                                               const float* __restrict__ wv,
                                               const float* __restrict__ wo) {
    const size_t i = ((size_t)blockIdx.x * 256 + threadIdx.x) * 8;
    const float* src;
    __half* dst;
    if (i < (size_t)Mtot * Dc) { src = x + i; dst = g_xh + i; }
    else {
        const size_t r = i - (size_t)Mtot * Dc;
        const int w = (int)(r >> 20);
        const size_t off = r & ((1u << 20) - 1);
        src = (w == 0 ? wq : w == 1 ? wk : w == 2 ? wv : wo) + off;
        dst = g_wh + r;
    }
    float4 a = *(const float4*)src, b = *(const float4*)(src + 4);
    __half2 h[4] = {__floats2half2_rn(a.x, a.y), __floats2half2_rn(a.z, a.w),
                    __floats2half2_rn(b.x, b.y), __floats2half2_rn(b.z, b.w)};
    *(uint4*)dst = *(uint4*)h;
}

// ---------------- fp16 GEMM: C = A @ B^T (fp32 accum) ----------------
// A: M x 1024 halves, B: 1024 x 1024 halves (row-major, K contig).
// Tile 128x128x64(K halves = 128B rows). XOR-swizzled 16B chunks, cp.async
// double buffer, ldmatrix.x4 operand fetch, 8 warps 2(m)x4(n), frag m16n8k16.
// QKV=1: blockIdx.z selects Wq/Wk/Wv, output to g_q/g_k/g_v in (B,H,T,dh).
// QKV=0: A=g_aoh, B=Wo, C=Cext row-major.
#define GSTAGE 32768             // bytes per stage (A 16K + B 16K)
#define GSMEM  65536

template<int QKV>
__global__ __launch_bounds__(256) void gemm_h(float* __restrict__ Cext) {
    extern __shared__ char gsm[];
    const int z = QKV ? blockIdx.z : 3;
    const __half* A = QKV ? g_xh : g_aoh;
    const __half* B = g_wh + (size_t)z * Dc * Dc;
    float* C = QKV ? (z == 0 ? g_q : z == 1 ? g_k : g_v) : Cext;

    const int tid = threadIdx.x, wid = tid >> 5, lane = tid & 31;
    const int row0 = blockIdx.y * 128, col0 = blockIdx.x * 128;
    const int wm = (wid & 1) * 64, wn = (wid >> 1) * 32;
    const int g = lane >> 2, tig = lane & 3;
    const uint32_t sbase = smem_u32(gsm);

    const __half* Ag = A + (size_t)row0 * Dc;
    const __half* Bg = B + (size_t)col0 * Dc;

    float acc[4][4][4];
    #pragma unroll
    for (int i = 0; i < 4; i++)
        #pragma unroll
        for (int j = 0; j < 4; j++)
            #pragma unroll
            for (int k = 0; k < 4; k++) acc[i][j][k] = 0.f;

    auto stage = [&](int kt) {
        const uint32_t sb = sbase + (kt & 1) * GSTAGE;
        #pragma unroll
        for (int p = 0; p < 4; p++) {
            const int ch = tid + 256 * p;
            const int r = ch >> 3, c = ch & 7;
            const uint32_t so = (uint32_t)(r * 128 + ((c ^ (r & 7)) << 4));
            cpa16(sb + so,         Ag + (size_t)r * Dc + kt * 64 + c * 8);
            cpa16(sb + 16384 + so, Bg + (size_t)r * Dc + kt * 64 + c * 8);
        }
        asm volatile("cp.async.commit_group;" ::: "memory");
    };

    stage(0);

    const int lrow = (lane & 7) + ((lane >> 3) & 1) * 8;  // row within 16-row tile
    const int lco  = (lane >> 4);                         // +8 halves for hi-k subs

    for (int kt = 0; kt < 16; kt++) {
        if (kt + 1 < 16) {
            stage(kt + 1);
            asm volatile("cp.async.wait_group 1;" ::: "memory");
        } else {
            asm volatile("cp.async.wait_group 0;" ::: "memory");
        }
        __syncthreads();

        const uint32_t sb = sbase + (kt & 1) * GSTAGE;
        #pragma unroll
        for (int ks = 0; ks < 4; ks++) {
            uint32_t af[4][4], bf[4][2];
            const int c = 2 * ks + lco;
            #pragma unroll
            for (int mi = 0; mi < 4; mi++) {
                const int r = wm + 16 * mi + lrow;
                LDMX4(af[mi], sb + r * 128 + ((c ^ (r & 7)) << 4));
            }
            #pragma unroll
            for (int np = 0; np < 2; np++) {
                const int r = wn + 16 * np + lrow;
                uint32_t t[4];
                LDMX4(t, sb + 16384 + r * 128 + ((c ^ (r & 7)) << 4));
                bf[2 * np][0] = t[0]; bf[2 * np][1] = t[2];
                bf[2 * np + 1][0] = t[1]; bf[2 * np + 1][1] = t[3];
            }
            #pragma unroll
            for (int mi = 0; mi < 4; mi++)
                #pragma unroll
                for (int ni = 0; ni < 4; ni++)
                    mma16(acc[mi][ni], af[mi], bf[ni]);
        }
        __syncthreads();
    }

    // epilogue: m16n8 frag: c0/c1 at (g, 2tig[+1]), c2/c3 at (g+8, ...)
    #pragma unroll
    for (int mi = 0; mi < 4; mi++) {
        #pragma unroll
        for (int ni = 0; ni < 4; ni++) {
            const int m0 = row0 + wm + mi * 16 + g;
            const int n  = col0 + wn + ni * 8 + tig * 2;
            float2 v01 = make_float2(acc[mi][ni][0], acc[mi][ni][1]);
            float2 v23 = make_float2(acc[mi][ni][2], acc[mi][ni][3]);
            if (QKV) {
                const int b0i = m0 >> 11, t0 = m0 & 2047;
                const int h = n / DH, d0 = n % DH;
                float* p0 = C + ((((size_t)(b0i * Hc + h)) * Tc + t0) * DH + d0);
                *(float2*)p0 = v01;
                const int m1 = m0 + 8;
                const int b1i = m1 >> 11, t1 = m1 & 2047;
                float* p1 = C + ((((size_t)(b1i * Hc + h)) * Tc + t1) * DH + d0);
                *(float2*)p1 = v23;
            } else {
                *(float2*)(C + (size_t)m0 * Dc + n) = v01;
                *(float2*)(C + (size_t)(m0 + 8) * Dc + n) = v23;
            }
        }
    }
}

// ---------------- tiled flash attention ----------------
// 128 threads per (b, h, 64-query tile). 3 key tiles of 64 cover [t0-128, t0+63].
// smem: Qt[d][q], KPt (K transposed during S; re-used as Pt[k][q] for PV), Vs[k][d].
#define ATS 68
#define ATT_SMEM (3*64*ATS*4)   // 52224 -> 4 CTAs/SM

__global__ __launch_bounds__(128) void attn_tile() {
    extern __shared__ float smA[];
    float* Qt  = smA;                 // [64 d][ATS]
    float* KPt = Qt + 64 * ATS;       // K^T during S phase; P^T during PV phase
    float* Vs  = KPt + 64 * ATS;      // [64 k][ATS]

    const int b = blockIdx.z, h = blockIdx.y;
    const int t0 = blockIdx.x * 64;
    const int tid = threadIdx.x;
    const int tx = tid & 7;           // 8 cols of 8
    const int ty = tid >> 3;          // 16 rows of 4
    const int w  = tid >> 5;          // warp id (rows 16w..16w+15)

    const size_t head_off = ((size_t)(b * Hc + h)) * Tc * DH;
    const float* qg = g_q + head_off;
    const float* kg = g_k + head_off;
    const float* vg = g_v + head_off;

    const int lr = tid >> 1;          // 0..63 staging row
    const int lcb = (tid & 1) * 32;   // float col base (half row)

    // stage Q transposed: Qt[d][q]
    {
        const float* src = qg + (size_t)(t0 + lr) * DH + lcb;
        #pragma unroll
        for (int i = 0; i < 8; i++) {
            float4 v = *(const float4*)(src + 4 * i);
            const int d = lcb + 4 * i;
            Qt[(d + 0) * ATS + lr] = v.x;
            Qt[(d + 1) * ATS + lr] = v.y;
            Qt[(d + 2) * ATS + lr] = v.z;
            Qt[(d + 3) * ATS + lr] = v.w;
        }
    }

    float m[4], l[4], acc[4][8];
    #pragma unroll
    for (int i = 0; i < 4; i++) {
        m[i] = -1e30f; l[i] = 0.f;
        #pragma unroll
        for (int j = 0; j < 8; j++) acc[i][j] = 0.f;
    }

    #pragma unroll 1
    for (int kt = 0; kt < 3; kt++) {
        const int kb = t0 - 128 + 64 * kt;

        // stage K transposed + V natural
        {
            const int gr = kb + lr;
            const int grc = gr < 0 ? 0 : gr;
            const float* ksrc = kg + (size_t)grc * DH + lcb;
            const float* vsrc = vg + (size_t)grc * DH + lcb;
            #pragma unroll
            for (int i = 0; i < 8; i++) {
                float4 kv = *(const float4*)(ksrc + 4 * i);
                const int d = lcb + 4 * i;
                KPt[(d + 0) * ATS + lr] = kv.x;
                KPt[(d + 1) * ATS + lr] = kv.y;
                KPt[(d + 2) * ATS + lr] = kv.z;
                KPt[(d + 3) * ATS + lr] = kv.w;
                float4 vv = *(const float4*)(vsrc + 4 * i);
                *(float4*)(Vs + lr * ATS + d) = vv;
            }
        }
        __syncthreads();

        // S = Q @ K^T: thread owns rows 4ty..+3, cols 8tx..+7
        float s[4][8];
        #pragma unroll
        for (int i = 0; i < 4; i++)
            #pragma unroll
            for (int j = 0; j < 8; j++) s[i][j] = 0.f;

        #pragma unroll 4
        for (int kk = 0; kk < 64; kk++) {
            float4 qv = *(const float4*)(Qt + kk * ATS + 4 * ty);
            float4 k0 = *(const float4*)(KPt + kk * ATS + 8 * tx);
            float4 k1 = *(const float4*)(KPt + kk * ATS + 8 * tx + 4);
            const float qr[4] = {qv.x, qv.y, qv.z, qv.w};
            const float kr[8] = {k0.x, k0.y, k0.z, k0.w, k1.x, k1.y, k1.z, k1.w};
            #pragma unroll
            for (int i = 0; i < 4; i++)
                #pragma unroll
                for (int j = 0; j < 8; j++)
                    s[i][j] = fmaf(qr[i], kr[j], s[i][j]);
        }
        __syncthreads();   // all warps done reading K before Pt overwrites it

        // mask + online softmax; write P transposed into KPt
        #pragma unroll
        for (int i = 0; i < 4; i++) {
            const int iq = t0 + 4 * ty + i;
            #pragma unroll
            for (int j = 0; j < 8; j++) {
                const int jq = kb + 8 * tx + j;
                const bool ok = (jq >= 0) & (jq <= iq) & (iq - jq <= 128);
                s[i][j] = ok ? s[i][j] * 0.125f : -1e30f;
            }
            float rmax = s[i][0];
            #pragma unroll
            for (int j = 1; j < 8; j++) rmax = fmaxf(rmax, s[i][j]);
            rmax = fmaxf(rmax, __shfl_xor_sync(0xffffffffu, rmax, 1));
            rmax = fmaxf(rmax, __shfl_xor_sync(0xffffffffu, rmax, 2));
            rmax = fmaxf(rmax, __shfl_xor_sync(0xffffffffu, rmax, 4));

            const float mn = fmaxf(m[i], rmax);
            const float corr = __expf(m[i] - mn);
            float rsum = 0.f;
            float p[8];
            #pragma unroll
            for (int j = 0; j < 8; j++) {
                p[j] = (s[i][j] > -1e29f) ? __expf(s[i][j] - mn) : 0.f;
                rsum += p[j];
            }
            rsum += __shfl_xor_sync(0xffffffffu, rsum, 1);
            rsum += __shfl_xor_sync(0xffffffffu, rsum, 2);
            rsum += __shfl_xor_sync(0xffffffffu, rsum, 4);
            l[i] = l[i] * corr + rsum;
            m[i] = mn;
            #pragma unroll
            for (int j = 0; j < 8; j++) acc[i][j] *= corr;
            #pragma unroll
            for (int j = 0; j < 8; j++)
                KPt[(8 * tx + j) * ATS + 4 * ty + i] = p[j];
        }
        __syncthreads();

        // O += P @ V: per-warp valid key range (window clipping)
        const int klo = max(0, 16 * w - 64 * kt);
        const int khi = min(64, 16 * w + 144 - 64 * kt);
        #pragma unroll 4
        for (int kk = klo; kk < khi; kk++) {
            float4 pv = *(const float4*)(KPt + kk * ATS + 4 * ty);
            float4 v0 = *(const float4*)(Vs + kk * ATS + 8 * tx);
            float4 v1 = *(const float4*)(Vs + kk * ATS + 8 * tx + 4);
            const float pr[4] = {pv.x, pv.y, pv.z, pv.w};
            const float vr[8] = {v0.x, v0.y, v0.z, v0.w, v1.x, v1.y, v1.z, v1.w};
            #pragma unroll
            for (int i = 0; i < 4; i++)
                #pragma unroll
                for (int j = 0; j < 8; j++)
                    acc[i][j] = fmaf(pr[i], vr[j], acc[i][j]);
        }
        __syncthreads();
    }

    // write O (fp16) for the Wo GEMM
    #pragma unroll
    for (int i = 0; i < 4; i++) {
        const float inv = 1.f / l[i];
        __half* dst = g_aoh + ((size_t)b * Tc + t0 + 4 * ty + i) * Dc + h * DH + 8 * tx;
        __half2 o[4] = {
            __floats2half2_rn(acc[i][0] * inv, acc[i][1] * inv),
            __floats2half2_rn(acc[i][2] * inv, acc[i][3] * inv),
            __floats2half2_rn(acc[i][4] * inv, acc[i][5] * inv),
            __floats2half2_rn(acc[i][6] * inv, acc[i][7] * inv)};
        *(uint4*)dst = *(uint4*)o;
    }
}

extern "C" void kernel_launch(void* const* d_in, const int* in_sizes, int n_in,
                              void* d_out, int out_size) {
    const float* x  = (const float*)d_in[0];
    const float* Wq = (const float*)d_in[1];
    const float* Wk = (const float*)d_in[2];
    const float* Wv = (const float*)d_in[3];
    const float* Wo = (const float*)d_in[4];
    float* out = (float*)d_out;

    cudaFuncSetAttribute(gemm_h<1>, cudaFuncAttributeMaxDynamicSharedMemorySize, GSMEM);
    cudaFuncSetAttribute(gemm_h<0>, cudaFuncAttributeMaxDynamicSharedMemorySize, GSMEM);
    cudaFuncSetAttribute(attn_tile, cudaFuncAttributeMaxDynamicSharedMemorySize, ATT_SMEM);

    // 8M floats to convert, 8 per thread
    cvt_all<<<4096, 256>>>(x, Wq, Wk, Wv, Wo);

    gemm_h<1><<<dim3(Dc / 128, Mtot / 128, 3), 256, GSMEM>>>(nullptr);

    attn_tile<<<dim3(Tc / 64, Hc, Bc), 128, ATT_SMEM>>>();

    gemm_h<0><<<dim3(Dc / 128, Mtot / 128), 256, GSMEM>>>(out);
}

// round 13
// speedup vs baseline: 10.5222x; 1.6159x over previous
#include <cuda_runtime.h>
#include <cuda_fp16.h>
#include <cstdint>
#include <math.h>

#define Bc 2
#define Tc 2048
#define Dc 1024
#define Hc 16
#define DH 64
#define Mtot (Bc*Tc)   // 4096

// Scratch (allocation-free)
__device__ __half g_xh [Mtot*Dc];        // x in fp16
__device__ __half g_wh [4*Dc*Dc];        // Wq,Wk,Wv,Wo in fp16
__device__ __half g_qh [Bc*Hc*Tc*DH];    // q (B,H,T,dh) fp16, pre-scaled by 1/8
__device__ __half g_kh [Bc*Hc*Tc*DH];
__device__ __half g_vh [Bc*Hc*Tc*DH];
__device__ __half g_aoh[Bc*Tc*Dc];       // attention output fp16

// ---------------- helpers ----------------
__device__ __forceinline__ uint32_t smem_u32(const void* p) {
    uint32_t a;
    asm("{ .reg .u64 t; cvta.to.shared.u64 t, %1; cvt.u32.u64 %0, t; }" : "=r"(a) : "l"(p));
    return a;
}
__device__ __forceinline__ void cpa16(uint32_t s, const void* gp) {
    asm volatile("cp.async.cg.shared.global [%0], [%1], 16;" :: "r"(s), "l"(gp) : "memory");
}
#define LDMX4(r, a) \
    asm volatile("ldmatrix.sync.aligned.m8n8.x4.shared.b16 {%0,%1,%2,%3}, [%4];" \
        : "=r"((r)[0]), "=r"((r)[1]), "=r"((r)[2]), "=r"((r)[3]) : "r"(a))

__device__ __forceinline__ void mma16(float* c, const uint32_t* a, uint32_t b0, uint32_t b1) {
    asm volatile(
        "mma.sync.aligned.m16n8k16.row.col.f32.f16.f16.f32 "
        "{%0,%1,%2,%3}, {%4,%5,%6,%7}, {%8,%9}, {%0,%1,%2,%3};"
        : "+f"(c[0]), "+f"(c[1]), "+f"(c[2]), "+f"(c[3])
        : "r"(a[0]), "r"(a[1]), "r"(a[2]), "r"(a[3]), "r"(b0), "r"(b1));
}
__device__ __forceinline__ uint32_t f2h2(float a, float b) {
    __half2 h = __floats2half2_rn(a, b);
    return *(uint32_t*)&h;
}

// ---------------- fp32 -> fp16 pre-convert ----------------
__global__ __launch_bounds__(256) void cvt_all(const float* __restrict__ x,
                                               const float* __restrict__ wq,
                                               const float* __restrict__ wk,
                                               const float* __restrict__ wv,
                                               const float* __restrict__ wo) {
    const size_t i = ((size_t)blockIdx.x * 256 + threadIdx.x) * 8;
    const float* src;
    __half* dst;
    if (i < (size_t)Mtot * Dc) { src = x + i; dst = g_xh + i; }
    else {
        const size_t r = i - (size_t)Mtot * Dc;
        const int w = (int)(r >> 20);
        const size_t off = r & ((1u << 20) - 1);
        src = (w == 0 ? wq : w == 1 ? wk : w == 2 ? wv : wo) + off;
        dst = g_wh + r;
    }
    float4 a = *(const float4*)src, b = *(const float4*)(src + 4);
    __half2 h[4] = {__floats2half2_rn(a.x, a.y), __floats2half2_rn(a.z, a.w),
                    __floats2half2_rn(b.x, b.y), __floats2half2_rn(b.z, b.w)};
    *(uint4*)dst = *(uint4*)h;
}

// ---------------- fp16 GEMM: C = A @ B^T, 3-stage cp.async ----------------
// Tile 128x128x64 halves. 8 warps 2(m)x4(n). QKV=1: z selects Wq/Wk/Wv,
// writes fp16 (B,H,T,dh) (q pre-scaled 1/8). QKV=0: g_aoh @ Wo^T -> fp32 out.
#define GSTAGE 32768
#define GSMEM  (3*GSTAGE)

template<int QKV>
__global__ __launch_bounds__(256) void gemm_h(float* __restrict__ Cext) {
    extern __shared__ char gsm[];
    const int z = QKV ? blockIdx.z : 3;
    const __half* A = QKV ? g_xh : g_aoh;
    const __half* B = g_wh + (size_t)z * Dc * Dc;

    const int tid = threadIdx.x, wid = tid >> 5, lane = tid & 31;
    const int row0 = blockIdx.y * 128, col0 = blockIdx.x * 128;
    const int wm = (wid & 1) * 64, wn = (wid >> 1) * 32;
    const int g = lane >> 2, tig = lane & 3;
    const uint32_t sbase = smem_u32(gsm);

    const __half* Ag = A + (size_t)row0 * Dc;
    const __half* Bg = B + (size_t)col0 * Dc;

    float acc[4][4][4];
    #pragma unroll
    for (int i = 0; i < 4; i++)
        #pragma unroll
        for (int j = 0; j < 4; j++)
            #pragma unroll
            for (int k = 0; k < 4; k++) acc[i][j][k] = 0.f;

    auto stage = [&](int kt) {
        const uint32_t sb = sbase + (kt % 3) * GSTAGE;
        #pragma unroll
        for (int p = 0; p < 4; p++) {
            const int ch = tid + 256 * p;
            const int r = ch >> 3, c = ch & 7;
            const uint32_t so = (uint32_t)(r * 128 + ((c ^ (r & 7)) << 4));
            cpa16(sb + so,         Ag + (size_t)r * Dc + kt * 64 + c * 8);
            cpa16(sb + 16384 + so, Bg + (size_t)r * Dc + kt * 64 + c * 8);
        }
        asm volatile("cp.async.commit_group;" ::: "memory");
    };

    stage(0);
    stage(1);

    const int lrow = (lane & 7) + ((lane >> 3) & 1) * 8;
    const int lco  = (lane >> 4);

    for (int kt = 0; kt < 16; kt++) {
        if (kt + 1 < 16) asm volatile("cp.async.wait_group 1;" ::: "memory");
        else             asm volatile("cp.async.wait_group 0;" ::: "memory");
        __syncthreads();
        if (kt + 2 < 16) stage(kt + 2);

        const uint32_t sb = sbase + (kt % 3) * GSTAGE;
        #pragma unroll
        for (int ks = 0; ks < 4; ks++) {
            uint32_t af[4][4], bf[4][2];
            const int c = 2 * ks + lco;
            #pragma unroll
            for (int mi = 0; mi < 4; mi++) {
                const int r = wm + 16 * mi + lrow;
                LDMX4(af[mi], sb + r * 128 + ((c ^ (r & 7)) << 4));
            }
            #pragma unroll
            for (int np = 0; np < 2; np++) {
                const int r = wn + 16 * np + lrow;
                uint32_t t[4];
                LDMX4(t, sb + 16384 + r * 128 + ((c ^ (r & 7)) << 4));
                bf[2 * np][0] = t[0]; bf[2 * np][1] = t[2];
                bf[2 * np + 1][0] = t[1]; bf[2 * np + 1][1] = t[3];
            }
            #pragma unroll
            for (int mi = 0; mi < 4; mi++)
                #pragma unroll
                for (int ni = 0; ni < 4; ni++)
                    mma16(acc[mi][ni], af[mi], bf[ni][0], bf[ni][1]);
        }
        __syncthreads();
    }

    const float sc = (QKV && z == 0) ? 0.125f : 1.f;
    __half* Hout = QKV ? (z == 0 ? g_qh : z == 1 ? g_kh : g_vh) : nullptr;

    #pragma unroll
    for (int mi = 0; mi < 4; mi++) {
        #pragma unroll
        for (int ni = 0; ni < 4; ni++) {
            const int m0 = row0 + wm + mi * 16 + g;
            const int n  = col0 + wn + ni * 8 + tig * 2;
            if (QKV) {
                const int b0i = m0 >> 11, t0q = m0 & 2047;
                const int h = n / DH, d0 = n % DH;
                __half* p0 = Hout + ((((size_t)(b0i * Hc + h)) * Tc + t0q) * DH + d0);
                *(uint32_t*)p0 = f2h2(acc[mi][ni][0] * sc, acc[mi][ni][1] * sc);
                const int m1 = m0 + 8;
                const int b1i = m1 >> 11, t1q = m1 & 2047;
                __half* p1 = Hout + ((((size_t)(b1i * Hc + h)) * Tc + t1q) * DH + d0);
                *(uint32_t*)p1 = f2h2(acc[mi][ni][2] * sc, acc[mi][ni][3] * sc);
            } else {
                *(float2*)(Cext + (size_t)m0 * Dc + n) =
                    make_float2(acc[mi][ni][0], acc[mi][ni][1]);
                *(float2*)(Cext + (size_t)(m0 + 8) * Dc + n) =
                    make_float2(acc[mi][ni][2], acc[mi][ni][3]);
            }
        }
    }
}

// ---------------- tensor-core flash attention ----------------
// 128 threads (4 warps) per (b, h, 64-query tile). Warp w owns queries
// 16w..16w+15. 3 key tiles of 64 cover [t0-128, t0+63].
// smem: Qs (64 rows x 128B), Ks (same), Vt (V transposed: rows d, cols key).
#define ATSM 24576

__global__ __launch_bounds__(128) void attn_tile() {
    extern __shared__ __align__(16) char asmem[];
    const uint32_t sb = smem_u32(asmem);

    const int b = blockIdx.z, h = blockIdx.y;
    const int t0 = blockIdx.x * 64;
    const int tid = threadIdx.x;
    const int w = tid >> 5, lane = tid & 31;
    const int g = lane >> 2, tig = lane & 3;
    const int lrow = (lane & 7) + ((lane >> 3) & 1) * 8;
    const int lco  = (lane >> 4);

    const size_t head_off = ((size_t)(b * Hc + h)) * Tc * DH;
    const __half* qg = g_qh + head_off;
    const __half* kg = g_kh + head_off;
    const __half* vg = g_vh + head_off;

    auto offb = [](int r, int ch) { return (uint32_t)(r * 128 + ((ch ^ (r & 7)) << 4)); };

    // stage Q (once)
    #pragma unroll
    for (int i = 0; i < 4; i++) {
        const int c = tid + 128 * i;
        const int r = c >> 3, ch = c & 7;
        *(uint4*)(asmem + offb(r, ch)) = *(const uint4*)(qg + (size_t)(t0 + r) * DH + ch * 8);
    }

    float mlo = -1e30f, mhi = -1e30f, llo = 0.f, lhi = 0.f;
    float oac[8][4];
    #pragma unroll
    for (int f = 0; f < 8; f++)
        #pragma unroll
        for (int k = 0; k < 4; k++) oac[f][k] = 0.f;

    const int iq0 = t0 + 16 * w + g;

    #pragma unroll 1
    for (int kt = 0; kt < 3; kt++) {
        const int kb = t0 - 128 + 64 * kt;

        // stage K (16B chunks) and V transposed (scalar)
        #pragma unroll
        for (int i = 0; i < 4; i++) {
            const int c = tid + 128 * i;
            const int r = c >> 3, ch = c & 7;
            const int gr = max(kb + r, 0);
            *(uint4*)(asmem + 8192 + offb(r, ch)) = *(const uint4*)(kg + (size_t)gr * DH + ch * 8);
        }
        {
            const int kr = tid >> 1;
            const int db = (tid & 1) * 32;
            const int gr = max(kb + kr, 0);
            const __half* vs = vg + (size_t)gr * DH + db;
            #pragma unroll
            for (int i = 0; i < 4; i++) {
                uint4 v = *(const uint4*)(vs + 8 * i);
                const __half* hv = (const __half*)&v;
                #pragma unroll
                for (int j = 0; j < 8; j++) {
                    const int d = db + 8 * i + j;
                    *(__half*)(asmem + 16384 + d * 128 + (((kr >> 3) ^ (d & 7)) << 4) + (kr & 7) * 2) = hv[j];
                }
            }
        }
        __syncthreads();

        const int lo = 16 * w - 64 * kt;          // min valid rel key for this warp
        const int hi = 16 * w + 143 - 64 * kt;    // max valid rel key

        // S = Q K^T (pre-scaled q), frag-clipped
        float sfr[8][4];
        #pragma unroll
        for (int f = 0; f < 8; f++)
            #pragma unroll
            for (int k = 0; k < 4; k++) sfr[f][k] = 0.f;

        #pragma unroll
        for (int ks = 0; ks < 4; ks++) {
            uint32_t aq[4];
            LDMX4(aq, sb + offb(16 * w + lrow, 2 * ks + lco));
            #pragma unroll
            for (int np = 0; np < 4; np++) {
                const bool f0v = (8 * (2 * np) + 7 >= lo) && (8 * (2 * np) <= hi);
                const bool f1v = (8 * (2 * np + 1) + 7 >= lo) && (8 * (2 * np + 1) <= hi);
                if (f0v || f1v) {
                    uint32_t t[4];
                    LDMX4(t, sb + 8192 + offb(16 * np + lrow, 2 * ks + lco));
                    if (f0v) mma16(sfr[2 * np],     aq, t[0], t[2]);
                    if (f1v) mma16(sfr[2 * np + 1], aq, t[1], t[3]);
                }
            }
        }

        // mask + online softmax; pack P into A-frags
        float rlo = -1e30f, rhi = -1e30f;
        #pragma unroll
        for (int f = 0; f < 8; f++) {
            const bool fv = (8 * f + 7 >= lo) && (8 * f <= hi);
            const int jb = kb + 8 * f + 2 * tig;
            if (fv) {
                if (!(jb     >= 0 && jb     <= iq0     && iq0     - jb     <= 128)) sfr[f][0] = -1e30f;
                if (!(jb + 1 >= 0 && jb + 1 <= iq0     && iq0     - jb - 1 <= 128)) sfr[f][1] = -1e30f;
                if (!(jb     >= 0 && jb     <= iq0 + 8 && iq0 + 8 - jb     <= 128)) sfr[f][2] = -1e30f;
                if (!(jb + 1 >= 0 && jb + 1 <= iq0 + 8 && iq0 + 8 - jb - 1 <= 128)) sfr[f][3] = -1e30f;
                rlo = fmaxf(rlo, fmaxf(sfr[f][0], sfr[f][1]));
                rhi = fmaxf(rhi, fmaxf(sfr[f][2], sfr[f][3]));
            }
        }
        rlo = fmaxf(rlo, __shfl_xor_sync(0xffffffffu, rlo, 1));
        rlo = fmaxf(rlo, __shfl_xor_sync(0xffffffffu, rlo, 2));
        rhi = fmaxf(rhi, __shfl_xor_sync(0xffffffffu, rhi, 1));
        rhi = fmaxf(rhi, __shfl_xor_sync(0xffffffffu, rhi, 2));

        const float mnlo = fmaxf(mlo, rlo), mnhi = fmaxf(mhi, rhi);
        const float clo = __expf(mlo - mnlo), chi = __expf(mhi - mnhi);

        uint32_t pa[4][4];
        float slo = 0.f, shi = 0.f;
        #pragma unroll
        for (int f = 0; f < 8; f++) {
            const bool fv = (8 * f + 7 >= lo) && (8 * f <= hi);
            float p0 = 0.f, p1 = 0.f, p2 = 0.f, p3 = 0.f;
            if (fv) {
                p0 = sfr[f][0] > -1e29f ? __expf(sfr[f][0] - mnlo) : 0.f;
                p1 = sfr[f][1] > -1e29f ? __expf(sfr[f][1] - mnlo) : 0.f;
                p2 = sfr[f][2] > -1e29f ? __expf(sfr[f][2] - mnhi) : 0.f;
                p3 = sfr[f][3] > -1e29f ? __expf(sfr[f][3] - mnhi) : 0.f;
                slo += p0 + p1; shi += p2 + p3;
            }
            pa[f >> 1][(f & 1) * 2]     = f2h2(p0, p1);
            pa[f >> 1][(f & 1) * 2 + 1] = f2h2(p2, p3);
        }
        slo += __shfl_xor_sync(0xffffffffu, slo, 1);
        slo += __shfl_xor_sync(0xffffffffu, slo, 2);
        shi += __shfl_xor_sync(0xffffffffu, shi, 1);
        shi += __shfl_xor_sync(0xffffffffu, shi, 2);

        llo = llo * clo + slo; lhi = lhi * chi + shi;
        mlo = mnlo; mhi = mnhi;
        #pragma unroll
        for (int f = 0; f < 8; f++) {
            oac[f][0] *= clo; oac[f][1] *= clo;
            oac[f][2] *= chi; oac[f][3] *= chi;
        }

        // O += P V  (B-operand = V^T in smem, same recipe as GEMM B)
        #pragma unroll
        for (int s = 0; s < 4; s++) {
            if (16 * s + 15 >= lo && 16 * s <= hi) {
                #pragma unroll
                for (int dj = 0; dj < 4; dj++) {
                    uint32_t t[4];
                    LDMX4(t, sb + 16384 + offb(16 * dj + lrow, 2 * s + lco));
                    mma16(oac[2 * dj],     pa[s], t[0], t[2]);
                    mma16(oac[2 * dj + 1], pa[s], t[1], t[3]);
                }
            }
        }
        __syncthreads();
    }

    // write O (fp16)
    const float ilo = 1.f / llo, ihi = 1.f / lhi;
    __half* o0 = g_aoh + ((size_t)b * Tc + t0 + 16 * w + g) * Dc + h * DH;
    __half* o1 = o0 + (size_t)8 * Dc;
    #pragma unroll
    for (int f = 0; f < 8; f++) {
        const int d0 = 8 * f + 2 * tig;
        *(uint32_t*)(o0 + d0) = f2h2(oac[f][0] * ilo, oac[f][1] * ilo);
        *(uint32_t*)(o1 + d0) = f2h2(oac[f][2] * ihi, oac[f][3] * ihi);
    }
}

extern "C" void kernel_launch(void* const* d_in, const int* in_sizes, int n_in,
                              void* d_out, int out_size) {
    const float* x  = (const float*)d_in[0];
    const float* Wq = (const float*)d_in[1];
    const float* Wk = (const float*)d_in[2];
    const float* Wv = (const float*)d_in[3];
    const float* Wo = (const float*)d_in[4];
    float* out = (float*)d_out;

    cudaFuncSetAttribute(gemm_h<1>, cudaFuncAttributeMaxDynamicSharedMemorySize, GSMEM);
    cudaFuncSetAttribute(gemm_h<0>, cudaFuncAttributeMaxDynamicSharedMemorySize, GSMEM);

    cvt_all<<<4096, 256>>>(x, Wq, Wk, Wv, Wo);

    gemm_h<1><<<dim3(Dc / 128, Mtot / 128, 3), 256, GSMEM>>>(nullptr);

    attn_tile<<<dim3(Tc / 64, Hc, Bc), 128, ATSM>>>();

    gemm_h<0><<<dim3(Dc / 128, Mtot / 128), 256, GSMEM>>>(out);
}